// round 17
// baseline (speedup 1.0000x reference)
#include <cuda_runtime.h>
#include <cstdint>
#include <cstddef>

// Problem constants
#define BATCH 4
#define SEQ   2048
#define EMB   512
#define HEADS 8
#define KDIM  64
#define TOKENS (BATCH * SEQ)          // 8192
#define BH    (BATCH * HEADS)         // 32

// Scratch (allocation-free rule: __device__ globals)
__device__ float g_q  [TOKENS * EMB];   // Q = x @ Wq, [tok, h*64+d]
__device__ float g_ctx[TOKENS * EMB];   // context,    [tok, h*64+d]
__device__ uint2 g_khl[BH * SEQ * 32];     // K: {hi,lo} per dpair, key-major
__device__ uint2 g_vhl[BH * 1024 * 64];    // V: {hi,lo} per (rowpair, dim)

// ---------------------------------------------------------------------------
// helpers
// ---------------------------------------------------------------------------
__device__ __forceinline__ uint32_t pack2(float lo, float hi) {
    uint32_t r;
    asm("cvt.rn.bf16x2.f32 %0, %1, %2;" : "=r"(r) : "f"(hi), "f"(lo));
    return r;
}
__device__ __forceinline__ float unlo(uint32_t p) { return __uint_as_float(p << 16); }
__device__ __forceinline__ float unhi(uint32_t p) { return __uint_as_float(p & 0xffff0000u); }
__device__ __forceinline__ uint32_t resid2(float lo, float hi, uint32_t h) {
    return pack2(lo - unlo(h), hi - unhi(h));
}
__device__ __forceinline__ void mma_bf16(float* c,
                                         uint32_t a0, uint32_t a1, uint32_t a2, uint32_t a3,
                                         uint32_t b0, uint32_t b1)
{
    asm volatile(
        "mma.sync.aligned.m16n8k16.row.col.f32.bf16.bf16.f32 "
        "{%0,%1,%2,%3}, {%4,%5,%6,%7}, {%8,%9}, {%0,%1,%2,%3};\n"
        : "+f"(c[0]), "+f"(c[1]), "+f"(c[2]), "+f"(c[3])
        : "r"(a0), "r"(a1), "r"(a2), "r"(a3), "r"(b0), "r"(b1));
}

// smem row widths
#define KW2 36   // K interleaved: [key][dpair] in uint2, 32 + 4 pad (72 words)
#define VW2I 68  // V interleaved: [rowpair][dim] in uint2, 64 + 4 pad (136 words)
#define VW2 136  // GEMM B-style (128-wide): [rowpair][col], uint32 words
#define AW  20   // GEMM A packed row width (uint32 words)

// ===========================================================================
// Pre-pack kernels: emit interleaved {hi,lo} uint2 planes.
// pack_cont_hl: pairs along contiguous dim. float4 -> uint4 {h0,l0,h1,l1}.
// pack_rows_hl: pairs of rows (stride W); two cols -> uint4 {h0,l0,h1,l1}.
// ===========================================================================
__global__ void pack_cont_hl(const float* __restrict__ src,
                             uint2* __restrict__ dst, int n4)
{
    int i = blockIdx.x * blockDim.x + threadIdx.x;
    if (i >= n4) return;
    float4 a = ((const float4*)src)[i];
    uint32_t h0 = pack2(a.x, a.y), h1 = pack2(a.z, a.w);
    ((uint4*)dst)[i] = make_uint4(h0, resid2(a.x, a.y, h0),
                                  h1, resid2(a.z, a.w, h1));
}
__global__ void pack_rows_hl(const float* __restrict__ src,
                             uint2* __restrict__ dst, int npairs2, int W)
{
    int j = blockIdx.x * blockDim.x + threadIdx.x;
    if (j >= npairs2) return;
    int i2 = 2 * j;
    int rp = i2 / W, d = i2 % W;
    float2 r0 = *(const float2*)&src[(size_t)(2 * rp) * W + d];
    float2 r1 = *(const float2*)&src[(size_t)(2 * rp + 1) * W + d];
    uint32_t h0 = pack2(r0.x, r1.x), h1 = pack2(r0.y, r1.y);
    ((uint4*)dst)[j] = make_uint4(h0, resid2(r0.x, r1.x, h0),
                                  h1, resid2(r0.y, r1.y, h1));
}

// ===========================================================================
// Split-bf16 GEMM (round-13 VERBATIM): C = A @ B, 128x128 tile, BK=32,
// single-wave grid (256 CTAs at 2 CTAs/SM).
// ===========================================================================
__global__ __launch_bounds__(256) void gemm_bf16s(
    const float* __restrict__ A, const float* __restrict__ Bm,
    float* __restrict__ C, int M, int N, int K)
{
    __shared__ uint32_t Ahi[128 * AW], Alo[128 * AW];
    __shared__ uint32_t Bhi[16 * VW2], Blo[16 * VW2];

    const int tid  = threadIdx.x;
    const int warp = tid >> 5, lane = tid & 31;
    const int g = lane >> 2, t = lane & 3;
    const int bn = blockIdx.x << 7;
    const int bm = blockIdx.y << 7;
    const int wm = warp << 4;

    const int cr = tid >> 1, c16 = (tid & 1) << 4;
    const int nn = (tid & 63) << 1, rr = (tid >> 6) << 3;

    float acc[16][4];
#pragma unroll
    for (int n = 0; n < 16; ++n)
#pragma unroll
        for (int i = 0; i < 4; ++i) acc[n][i] = 0.f;

    for (int kt = 0; kt < K; kt += 32) {
        __syncthreads();
        {
            const float* ar = &A[(size_t)(bm + cr) * K + kt + c16];
#pragma unroll
            for (int i = 0; i < 4; ++i) {
                float4 a = *(const float4*)&ar[4 * i];
                uint32_t h0 = pack2(a.x, a.y), h1 = pack2(a.z, a.w);
                int w = cr * AW + (c16 >> 1) + 2 * i;
                *(uint2*)&Ahi[w] = make_uint2(h0, h1);
                *(uint2*)&Alo[w] = make_uint2(resid2(a.x, a.y, h0), resid2(a.z, a.w, h1));
            }
#pragma unroll
            for (int i = 0; i < 4; ++i) {
                int r0 = rr + 2 * i;
                float2 p = *(const float2*)&Bm[(size_t)(kt + r0)     * N + bn + nn];
                float2 q = *(const float2*)&Bm[(size_t)(kt + r0 + 1) * N + bn + nn];
                uint32_t h0 = pack2(p.x, q.x), h1 = pack2(p.y, q.y);
                int w = (r0 >> 1) * VW2 + nn;
                *(uint2*)&Bhi[w] = make_uint2(h0, h1);
                *(uint2*)&Blo[w] = make_uint2(resid2(p.x, q.x, h0), resid2(p.y, q.y, h1));
            }
        }
        __syncthreads();

#pragma unroll
        for (int kc = 0; kc < 2; ++kc) {
            const int wa = (wm + g) * AW + kc * 8 + t;
            uint32_t ah0 = Ahi[wa],     ah1 = Ahi[wa + 8 * AW];
            uint32_t ah2 = Ahi[wa + 4], ah3 = Ahi[wa + 8 * AW + 4];
            uint32_t al0 = Alo[wa],     al1 = Alo[wa + 8 * AW];
            uint32_t al2 = Alo[wa + 4], al3 = Alo[wa + 8 * AW + 4];
#pragma unroll
            for (int n = 0; n < 16; ++n) {
                const int wb = (kc * 8 + t) * VW2 + n * 8 + g;
                uint32_t bh0 = Bhi[wb], bh1 = Bhi[wb + 4 * VW2];
                uint32_t bl0 = Blo[wb], bl1 = Blo[wb + 4 * VW2];
                mma_bf16(acc[n], ah0, ah1, ah2, ah3, bh0, bh1);
                mma_bf16(acc[n], al0, al1, al2, al3, bh0, bh1);
                mma_bf16(acc[n], ah0, ah1, ah2, ah3, bl0, bl1);
            }
        }
    }

    const int row0 = bm + wm + g, row1 = row0 + 8;
#pragma unroll
    for (int n = 0; n < 16; ++n) {
        *(float2*)&C[(size_t)row0 * N + bn + n * 8 + 2 * t] = make_float2(acc[n][0], acc[n][1]);
        *(float2*)&C[(size_t)row1 * N + bn + n * 8 + 2 * t] = make_float2(acc[n][2], acc[n][3]);
    }
}

// ===========================================================================
// Flash attention: interleaved {hi,lo} K/V smem — each fragment operand pair
// is ONE LDS.64 (mainloop LDS count halved vs round 16). Values and mma order
// bit-identical to round 16. 2 CTAs/SM via __launch_bounds__(256,2).
// Bank check (16-lane LDS.64 phases): K stride 72 words -> banks 8g+2t+{0,1}
// cover 32 exactly; V stride 136 -> 8t+2g+{0,1} likewise.
// ===========================================================================
__global__ __launch_bounds__(256, 2) void attn_mma(
    const float* __restrict__ Q,          // [tok, 512] fp32 from g_q
    const uint2* __restrict__ Khlg, const uint2* __restrict__ Vhlg,
    float* __restrict__ Ctx)              // [tok, 512] fp32
{
    __shared__ uint2 Khl[64 * KW2];    // [key][dpair]   18432 B
    __shared__ uint2 Vhl[32 * VW2I];   // [rowpair][dim] 17408 B

    const int tid  = threadIdx.x;
    const int warp = tid >> 5, lane = tid & 31;
    const int gq = lane >> 2, tq = lane & 3;
    const int bh = blockIdx.y;
    const int b  = bh >> 3, h = bh & 7;
    const int q0 = blockIdx.x << 7;
    const int row0 = q0 + warp * 16 + gq;
    const int row1 = row0 + 8;

    const uint2* khb = Khlg + (size_t)bh * SEQ * 32;
    const uint2* vhb = Vhlg + (size_t)bh * 1024 * 64;

    // fill mappings (pure uint4 copy)
    const int fk = tid >> 2, fkp = (tid & 3) << 3;    // K: key, dpair base (x8)
    const int fv = tid >> 3, fvd = (tid & 7) << 3;    // V: rowpair, dim base (x8)

    // ---- Q fragments (bf16 hi/lo), pre-scaled by 1/sqrt(64) ----
    uint32_t qh[4][4], ql[4][4];
    {
        const float* qp = Q + (size_t)(b * SEQ) * EMB + h * KDIM;
#pragma unroll
        for (int kc = 0; kc < 4; ++kc) {
            float2 v0 = *(const float2*)&qp[(size_t)row0 * EMB + kc * 16 + 2 * tq];
            float2 v1 = *(const float2*)&qp[(size_t)row1 * EMB + kc * 16 + 2 * tq];
            float2 v2 = *(const float2*)&qp[(size_t)row0 * EMB + kc * 16 + 2 * tq + 8];
            float2 v3 = *(const float2*)&qp[(size_t)row1 * EMB + kc * 16 + 2 * tq + 8];
            v0.x *= 0.125f; v0.y *= 0.125f; v1.x *= 0.125f; v1.y *= 0.125f;
            v2.x *= 0.125f; v2.y *= 0.125f; v3.x *= 0.125f; v3.y *= 0.125f;
            qh[kc][0] = pack2(v0.x, v0.y); ql[kc][0] = resid2(v0.x, v0.y, qh[kc][0]);
            qh[kc][1] = pack2(v1.x, v1.y); ql[kc][1] = resid2(v1.x, v1.y, qh[kc][1]);
            qh[kc][2] = pack2(v2.x, v2.y); ql[kc][2] = resid2(v2.x, v2.y, qh[kc][2]);
            qh[kc][3] = pack2(v3.x, v3.y); ql[kc][3] = resid2(v3.x, v3.y, qh[kc][3]);
        }
    }

    float oacc[8][4];
#pragma unroll
    for (int n = 0; n < 8; ++n)
#pragma unroll
        for (int i = 0; i < 4; ++i) oacc[n][i] = 0.f;
    float m0 = -1e30f, m1 = -1e30f, l0 = 0.f, l1 = 0.f;

    for (int kt = 0; kt < SEQ / 64; ++kt) {
        __syncthreads();
        {   // K tile fill: 64 keys x 32 dpairs (8 dpairs = 4 uint4 per thread)
            const uint4* src = (const uint4*)&khb[(size_t)(kt * 64 + fk) * 32 + fkp];
            uint4* dst = (uint4*)&Khl[fk * KW2 + fkp];
            dst[0] = src[0]; dst[1] = src[1]; dst[2] = src[2]; dst[3] = src[3];
            // V tile fill: 32 rowpairs x 64 dims
            const uint4* vsrc = (const uint4*)&vhb[(size_t)(kt * 32 + fv) * 64 + fvd];
            uint4* vdst = (uint4*)&Vhl[fv * VW2I + fvd];
            vdst[0] = vsrc[0]; vdst[1] = vsrc[1]; vdst[2] = vsrc[2]; vdst[3] = vsrc[3];
        }
        __syncthreads();

        // ---- S = Q K^T (16x64 per warp); 2 LDS.64 per mma-trio ----
        float sacc[8][4];
#pragma unroll
        for (int n = 0; n < 8; ++n)
#pragma unroll
            for (int i = 0; i < 4; ++i) sacc[n][i] = 0.f;

#pragma unroll
        for (int kc = 0; kc < 4; ++kc) {
#pragma unroll
            for (int n = 0; n < 8; ++n) {
                const uint2* kp = &Khl[(n * 8 + gq) * KW2 + kc * 8 + tq];
                uint2 b0 = kp[0], b1 = kp[4];
                mma_bf16(sacc[n], qh[kc][0], qh[kc][1], qh[kc][2], qh[kc][3], b0.x, b1.x);
                mma_bf16(sacc[n], ql[kc][0], ql[kc][1], ql[kc][2], ql[kc][3], b0.x, b1.x);
                mma_bf16(sacc[n], qh[kc][0], qh[kc][1], qh[kc][2], qh[kc][3], b0.y, b1.y);
            }
        }

        // ---- online softmax (quad-reduce; row0 via c0/c1, row1 via c2/c3) ----
        float tm0 = -1e30f, tm1 = -1e30f;
#pragma unroll
        for (int n = 0; n < 8; ++n) {
            tm0 = fmaxf(tm0, fmaxf(sacc[n][0], sacc[n][1]));
            tm1 = fmaxf(tm1, fmaxf(sacc[n][2], sacc[n][3]));
        }
        tm0 = fmaxf(tm0, __shfl_xor_sync(0xffffffffu, tm0, 1));
        tm0 = fmaxf(tm0, __shfl_xor_sync(0xffffffffu, tm0, 2));
        tm1 = fmaxf(tm1, __shfl_xor_sync(0xffffffffu, tm1, 1));
        tm1 = fmaxf(tm1, __shfl_xor_sync(0xffffffffu, tm1, 2));
        float n0 = fmaxf(m0, tm0), n1 = fmaxf(m1, tm1);
        float sc0 = __expf(m0 - n0), sc1 = __expf(m1 - n1);
        m0 = n0; m1 = n1;
        float ps0 = 0.f, ps1 = 0.f;
#pragma unroll
        for (int n = 0; n < 8; ++n) {
            sacc[n][0] = __expf(sacc[n][0] - n0); ps0 += sacc[n][0];
            sacc[n][1] = __expf(sacc[n][1] - n0); ps0 += sacc[n][1];
            sacc[n][2] = __expf(sacc[n][2] - n1); ps1 += sacc[n][2];
            sacc[n][3] = __expf(sacc[n][3] - n1); ps1 += sacc[n][3];
        }
        ps0 += __shfl_xor_sync(0xffffffffu, ps0, 1);
        ps0 += __shfl_xor_sync(0xffffffffu, ps0, 2);
        ps1 += __shfl_xor_sync(0xffffffffu, ps1, 1);
        ps1 += __shfl_xor_sync(0xffffffffu, ps1, 2);
        l0 = l0 * sc0 + ps0;
        l1 = l1 * sc1 + ps1;
#pragma unroll
        for (int n = 0; n < 8; ++n) {
            oacc[n][0] *= sc0; oacc[n][1] *= sc0;
            oacc[n][2] *= sc1; oacc[n][3] *= sc1;
        }

        // ---- O += P V : P accumulator pairs are A fragments; 2 LDS.64 each ----
#pragma unroll
        for (int j = 0; j < 4; ++j) {
            uint32_t ph0 = pack2(sacc[2*j][0],   sacc[2*j][1]);
            uint32_t ph1 = pack2(sacc[2*j][2],   sacc[2*j][3]);
            uint32_t ph2 = pack2(sacc[2*j+1][0], sacc[2*j+1][1]);
            uint32_t ph3 = pack2(sacc[2*j+1][2], sacc[2*j+1][3]);
            uint32_t pl0 = resid2(sacc[2*j][0],   sacc[2*j][1],   ph0);
            uint32_t pl1 = resid2(sacc[2*j][2],   sacc[2*j][3],   ph1);
            uint32_t pl2 = resid2(sacc[2*j+1][0], sacc[2*j+1][1], ph2);
            uint32_t pl3 = resid2(sacc[2*j+1][2], sacc[2*j+1][3], ph3);
#pragma unroll
            for (int dt = 0; dt < 8; ++dt) {
                uint2 v0 = Vhl[(j * 8 + tq)     * VW2I + dt * 8 + gq];
                uint2 v1 = Vhl[(j * 8 + tq + 4) * VW2I + dt * 8 + gq];
                mma_bf16(oacc[dt], ph0, ph1, ph2, ph3, v0.x, v1.x);
                mma_bf16(oacc[dt], pl0, pl1, pl2, pl3, v0.x, v1.x);
                mma_bf16(oacc[dt], ph0, ph1, ph2, ph3, v0.y, v1.y);
            }
        }
    }

    // ---- normalize + write ctx [tok, h*64+d] ----
    float inv0 = 1.f / l0, inv1 = 1.f / l1;
    float* cp = Ctx + (size_t)(b * SEQ) * EMB + h * KDIM;
#pragma unroll
    for (int dt = 0; dt < 8; ++dt) {
        *(float2*)&cp[(size_t)row0 * EMB + dt * 8 + 2 * tq] =
            make_float2(oacc[dt][0] * inv0, oacc[dt][1] * inv0);
        *(float2*)&cp[(size_t)row1 * EMB + dt * 8 + 2 * tq] =
            make_float2(oacc[dt][2] * inv1, oacc[dt][3] * inv1);
    }
}

// ---------------------------------------------------------------------------
extern "C" void kernel_launch(void* const* d_in, const int* in_sizes, int n_in,
                              void* d_out, int out_size)
{
    const float* x   = (const float*)d_in[0];   // [4,2048,512]
    const float* key = (const float*)d_in[1];   // [4,8,2048,64]
    const float* val = (const float*)d_in[2];   // [4,8,2048,64]
    const float* wq  = (const float*)d_in[3];   // [512,512]
    const float* wo  = (const float*)d_in[4];   // [512,512]
    float* out = (float*)d_out;                 // [4,2048,512]

    float *qptr, *cptr;
    uint2 *khl, *vhl;
    cudaGetSymbolAddress((void**)&qptr, g_q);
    cudaGetSymbolAddress((void**)&cptr, g_ctx);
    cudaGetSymbolAddress((void**)&khl, g_khl);
    cudaGetSymbolAddress((void**)&vhl, g_vhl);

    // ---- pre-pack K (contiguous dpairs) and V (rowpairs), interleaved ----
    const int n4k  = BH * SEQ * KDIM / 4;   // 1,048,576 float4s
    const int np2v = BH * SEQ * KDIM / 4;   // 1,048,576 word-pairs
    pack_cont_hl<<<(n4k  + 255) / 256, 256>>>(key, khl, n4k);
    pack_rows_hl<<<(np2v + 255) / 256, 256>>>(val, vhl, np2v, KDIM);

    // 1) Q = x @ Wq  (round-13 GEMM, single-wave 128x128)
    gemm_bf16s<<<dim3(EMB / 128, TOKENS / 128), 256>>>(x, wq, qptr, TOKENS, EMB, EMB);
    // 2) attention (interleaved pre-packed K/V; 2 CTAs/SM)
    attn_mma<<<dim3(SEQ / 128, BH), 256>>>(qptr, khl, vhl, cptr);
    // 3) out = ctx @ Wo
    gemm_bf16s<<<dim3(EMB / 128, TOKENS / 128), 256>>>(cptr, wo, out, TOKENS, EMB, EMB);
}